// round 6
// baseline (speedup 1.0000x reference)
#include <cuda_runtime.h>
#include <cstdint>
#include <cstddef>

// ---------------- problem constants ----------------
#define B_DIM 1024
#define V_DIM 50000
#define D_DIM 300
#define EPS   1e-7f

#define K_BLK   40                    // K per pipeline stage (5 k8 groups)
#define NKB     (V_DIM / K_BLK)       // 1250 stages total (exact: 40*1250=50000)
#define NSPLIT  18                    // split-K factor
#define M_TILE  128
#define M_TILES (B_DIM / M_TILE)      // 8   -> grid 8 x 18 = 144 CTAs (one wave)
#define N_PAD   320                   // N padded to 40 n8-fragments
#define D_PITCH 304                   // partials pitch

// ---- packed-B layout (float2 units; float2 = {B[k][n], B[k+4][n]}) ----
// per stage: q(k8 group 0..4) stride, tig(k%4) stride, g(n%8) stride, f(n/8)
#define G_STRIDE   40                 // f runs 0..39 (16g%32 bank-clean octets)
#define TIG_STRIDE 322                // 8*40=320 + 2 pad (bank offset 4/tig)
#define Q_STRIDE   (4 * TIG_STRIDE)   // 1288
#define STAGE_F2   (5 * Q_STRIDE)     // 6440 float2
#define STAGE_B_BYTES (STAGE_F2 * 8)  // 51520 bytes

// ---- GEMM smem layout ----
#define A_PITCH_F  44                 // floats per A row (bank-clean: 12m+k distinct)
#define A_STAGE_BYTES (M_TILE * A_PITCH_F * 4)   // 22528
#define SMEM_A(buf) ((uint32_t)(buf) * A_STAGE_BYTES)
#define SMEM_B(buf) (2u * A_STAGE_BYTES + (uint32_t)(buf) * STAGE_B_BYTES)
#define SMEM_TOTAL  (2 * A_STAGE_BYTES + 2 * STAGE_B_BYTES)  // 148096

// ---------------- device scratch (static: no runtime alloc) ----------------
__device__ __align__(16) float2 g_Bp[(size_t)NKB * STAGE_F2];          // ~64.4 MB
__device__ float g_colsum[D_PITCH];
__device__ __align__(16) float g_part[(size_t)NSPLIT * B_DIM * D_PITCH]; // ~22.4 MB

// ---------------- helpers ----------------
__device__ __forceinline__ uint32_t smem_u32(const void* p) {
    uint32_t a;
    asm("{ .reg .u64 t; cvta.to.shared.u64 t, %1; cvt.u32.u64 %0, t; }" : "=r"(a) : "l"(p));
    return a;
}
__device__ __forceinline__ void cp16(uint32_t dst, const void* src) {
    asm volatile("cp.async.cg.shared.global [%0], [%1], 16;" :: "r"(dst), "l"(src));
}
__device__ __forceinline__ uint32_t f2tf32(float x) {
    uint32_t r;
    asm("cvt.rna.tf32.f32 %0, %1;" : "=r"(r) : "f"(x));
    return r;
}
__device__ __forceinline__ void mma_tf32(float c[4], uint32_t a0, uint32_t a1,
                                         uint32_t a2, uint32_t a3,
                                         uint32_t b0, uint32_t b1) {
    asm volatile(
        "mma.sync.aligned.m16n8k8.row.col.f32.tf32.tf32.f32 "
        "{%0,%1,%2,%3}, {%4,%5,%6,%7}, {%8,%9}, {%0,%1,%2,%3};"
        : "+f"(c[0]), "+f"(c[1]), "+f"(c[2]), "+f"(c[3])
        : "r"(a0), "r"(a1), "r"(a2), "r"(a3), "r"(b0), "r"(b1));
}

// ---------------- kernel 0: zero colsum ----------------
__global__ void zero_colsum_kernel() {
    if (threadIdx.x < D_PITCH) g_colsum[threadIdx.x] = 0.0f;
}

// ---------------- kernel 1: pack W -> g_Bp (tf32-rounded) + colsum ----------------
// block kb handles W rows [kb*40, kb*40+40). Loads coalesced into smem,
// writes the exact GEMM smem stage image coalesced, accumulates column sums.
__global__ void __launch_bounds__(256) prep_kernel(const float* __restrict__ W) {
    __shared__ float raw[K_BLK][D_DIM];   // 48000 B
    const int kb = blockIdx.x;
    const int tid = threadIdx.x;
    const int v0 = kb * K_BLK;

    // load 40x300 floats as float4 (300 = 75 * 4, rows 16B-aligned)
    for (int i = tid; i < K_BLK * 75; i += 256) {
        int r = i / 75, c4 = i % 75;
        float4 v = *reinterpret_cast<const float4*>(W + (size_t)(v0 + r) * D_DIM + c4 * 4);
        *reinterpret_cast<float4*>(&raw[r][c4 * 4]) = v;
    }
    __syncthreads();

    // column sums (exact fp32 W)
    for (int n = tid; n < D_DIM; n += 256) {
        float s = 0.0f;
#pragma unroll
        for (int r = 0; r < K_BLK; r++) s += raw[r][n];
        atomicAdd(&g_colsum[n], s);
    }

    // pack (coalesced writes; scattered smem reads are cheap)
    float2* dst = g_Bp + (size_t)kb * STAGE_F2;
    for (int d = tid; d < STAGE_F2; d += 256) {
        int q  = d / Q_STRIDE;   int r1 = d - q * Q_STRIDE;
        int tg = r1 / TIG_STRIDE; int r2 = r1 - tg * TIG_STRIDE;
        int gg = r2 / G_STRIDE;   int f  = r2 - gg * G_STRIDE;
        float2 val = make_float2(0.0f, 0.0f);
        if (gg < 8) {
            int n = gg + 8 * f;                 // n in [0, 320)
            if (n < D_DIM) {
                val.x = __uint_as_float(f2tf32(raw[q * 8 + tg][n]));
                val.y = __uint_as_float(f2tf32(raw[q * 8 + tg + 4][n]));
            }
        }
        dst[d] = val;
    }
}

// ---------------- kernel 2: split-K tf32 GEMM via mma.sync ----------------
__device__ __forceinline__ void load_stage(uint32_t sb, const float* __restrict__ A,
                                           int m0, int kb, int buf) {
    const int tid = threadIdx.x;
    const uint32_t a_s = sb + SMEM_A(buf);
    const uint32_t b_s = sb + SMEM_B(buf);
    const int k0 = kb * K_BLK;
    // A: 128 rows x 160B = 1280 x 16B chunks (exactly 5 per thread)
#pragma unroll
    for (int it = 0; it < 5; it++) {
        int i = tid + it * 256;
        int r = i / 10, c = i - r * 10;
        cp16(a_s + (uint32_t)(r * (A_PITCH_F * 4) + c * 16),
             A + (size_t)(m0 + r) * V_DIM + k0 + c * 4);
    }
    // B: contiguous stage image, 3220 x 16B chunks
    const char* bsrc = (const char*)(g_Bp + (size_t)kb * STAGE_F2);
#pragma unroll
    for (int it = 0; it < 13; it++) {
        int i = tid + it * 256;
        if (i < STAGE_B_BYTES / 16) cp16(b_s + (uint32_t)(i * 16), bsrc + (size_t)i * 16);
    }
}

__global__ void __launch_bounds__(256, 1)
gemm_kernel(const float* __restrict__ A) {
    extern __shared__ char smem[];
    const uint32_t sb = smem_u32(smem);
    const int tid  = threadIdx.x;
    const int wid  = tid >> 5, lane = tid & 31;
    const int g    = lane >> 2, tig = lane & 3;
    const int wm   = wid & 3;     // 4 M-warps x m32
    const int wn   = wid >> 2;    // 2 N-warps x n160 (20 frags)

    const int m0 = blockIdx.x * M_TILE;
    const int z  = blockIdx.y;
    const int base = NKB / NSPLIT, rem = NKB % NSPLIT;   // 69, 8
    const int t0 = z * base + (z < rem ? z : rem);
    const int T  = base + (z < rem ? 1 : 0);

    float acc[2][20][4];
#pragma unroll
    for (int mf = 0; mf < 2; mf++)
#pragma unroll
        for (int f = 0; f < 20; f++)
#pragma unroll
            for (int j = 0; j < 4; j++) acc[mf][f][j] = 0.0f;

    load_stage(sb, A, m0, t0, 0);
    asm volatile("cp.async.commit_group;");

    for (int i = 0; i < T; i++) {
        const int buf = i & 1;
        if (i + 1 < T) {
            load_stage(sb, A, m0, t0 + i + 1, buf ^ 1);
            asm volatile("cp.async.commit_group;");
            asm volatile("cp.async.wait_group 1;");
        } else {
            asm volatile("cp.async.wait_group 0;");
        }
        __syncthreads();

        const uint32_t a_s = sb + SMEM_A(buf);
        const uint32_t b_s = sb + SMEM_B(buf);
#pragma unroll
        for (int q = 0; q < 5; q++) {
            // A fragments (centered by 0.5, tf32-rounded)
            uint32_t a[2][4];
#pragma unroll
            for (int mf = 0; mf < 2; mf++) {
                const uint32_t base_addr =
                    a_s + (uint32_t)((wm * 32 + mf * 16 + g) * (A_PITCH_F * 4) +
                                     (q * 8 + tig) * 4);
                float f0, f1, f2, f3;
                asm volatile("ld.shared.f32 %0, [%1];" : "=f"(f0) : "r"(base_addr));
                asm volatile("ld.shared.f32 %0, [%1];" : "=f"(f1) : "r"(base_addr + 8u * A_PITCH_F * 4u));
                asm volatile("ld.shared.f32 %0, [%1];" : "=f"(f2) : "r"(base_addr + 16u));
                asm volatile("ld.shared.f32 %0, [%1];" : "=f"(f3) : "r"(base_addr + 8u * A_PITCH_F * 4u + 16u));
                a[mf][0] = f2tf32(f0 - 0.5f);
                a[mf][1] = f2tf32(f1 - 0.5f);
                a[mf][2] = f2tf32(f2 - 0.5f);
                a[mf][3] = f2tf32(f3 - 0.5f);
            }
            // B fragments: 20 frags = 10 x ld.shared.v4 (2 frags each), then MMAs
#pragma unroll
            for (int fp = 0; fp < 10; fp++) {
                const int F0 = wn * 20 + fp * 2;
                const uint32_t baddr =
                    b_s + (uint32_t)((q * Q_STRIDE + tig * TIG_STRIDE + g * G_STRIDE + F0) * 8);
                uint32_t b00, b01, b10, b11;
                asm volatile("ld.shared.v4.b32 {%0,%1,%2,%3}, [%4];"
                             : "=r"(b00), "=r"(b01), "=r"(b10), "=r"(b11)
                             : "r"(baddr));
#pragma unroll
                for (int mf = 0; mf < 2; mf++) {
                    mma_tf32(acc[mf][fp * 2 + 0], a[mf][0], a[mf][1], a[mf][2], a[mf][3], b00, b01);
                    mma_tf32(acc[mf][fp * 2 + 1], a[mf][0], a[mf][1], a[mf][2], a[mf][3], b10, b11);
                }
            }
        }
        __syncthreads();
    }

    // epilogue: write split-K partials (disjoint slices, plain stores)
    float* part = g_part + (size_t)z * B_DIM * D_PITCH;
#pragma unroll
    for (int mf = 0; mf < 2; mf++) {
#pragma unroll
        for (int f = 0; f < 20; f++) {
            const int n = (wn * 20 + f) * 8 + 2 * tig;
            if (n < D_DIM) {
                const int r0 = m0 + wm * 32 + mf * 16 + g;
                *reinterpret_cast<float2*>(part + (size_t)r0 * D_PITCH + n) =
                    make_float2(acc[mf][f][0], acc[mf][f][1]);
                *reinterpret_cast<float2*>(part + (size_t)(r0 + 8) * D_PITCH + n) =
                    make_float2(acc[mf][f][2], acc[mf][f][3]);
            }
        }
    }
}

// ---------------- kernel 3: reduce split-K + colsum correction + L2 normalize ----------------
__global__ void __launch_bounds__(128) normalize_kernel(float* __restrict__ out) {
    __shared__ float red[4];
    const int r = blockIdx.x, tid = threadIdx.x;
    float vals[3];
    float ss = 0.0f;
#pragma unroll
    for (int j = 0; j < 3; j++) {
        const int n = tid + j * 128;
        float v = 0.0f;
        if (n < D_DIM) {
            v = 0.5f * g_colsum[n];
            for (int z = 0; z < NSPLIT; z++)
                v += g_part[((size_t)z * B_DIM + r) * D_PITCH + n];
        }
        vals[j] = v;
        ss += v * v;
    }
#pragma unroll
    for (int o = 16; o; o >>= 1) ss += __shfl_xor_sync(0xffffffffu, ss, o);
    if ((tid & 31) == 0) red[tid >> 5] = ss;
    __syncthreads();
    const float tot = red[0] + red[1] + red[2] + red[3];
    const float inv = 1.0f / (sqrtf(tot) + EPS);
#pragma unroll
    for (int j = 0; j < 3; j++) {
        const int n = tid + j * 128;
        if (n < D_DIM) out[(size_t)r * D_DIM + n] = vals[j] * inv;
    }
}

// ---------------- host launch ----------------
extern "C" void kernel_launch(void* const* d_in, const int* in_sizes, int n_in,
                              void* d_out, int out_size) {
    const float* labels = (const float*)d_in[0];
    const float* weight = (const float*)d_in[1];
    if (n_in >= 2 && in_sizes[0] == V_DIM * D_DIM) {  // defensive order swap
        const float* t = labels; labels = weight; weight = t;
    }

    static bool attr_set = false;
    if (!attr_set) {
        cudaFuncSetAttribute(gemm_kernel, cudaFuncAttributeMaxDynamicSharedMemorySize,
                             SMEM_TOTAL);
        attr_set = true;
    }

    zero_colsum_kernel<<<1, D_PITCH>>>();
    prep_kernel<<<NKB, 256>>>(weight);
    gemm_kernel<<<dim3(M_TILES, NSPLIT), 256, SMEM_TOTAL>>>(labels);
    normalize_kernel<<<B_DIM, 128>>>((float*)d_out);
}

// round 8
// speedup vs baseline: 1.0431x; 1.0431x over previous
#include <cuda_runtime.h>
#include <cstdint>
#include <cstddef>

// ---------------- problem constants ----------------
#define B_DIM 1024
#define V_DIM 50000
#define D_DIM 300
#define EPS   1e-7f

#define K_BLK   40                    // K per pipeline stage (5 k8 groups)
#define NKB     (V_DIM / K_BLK)       // 1250 stages total (exact: 40*1250=50000)
#define NSPLIT  18                    // split-K factor
#define M_TILE  128
#define M_TILES (B_DIM / M_TILE)      // 8   -> grid 8 x 18 = 144 CTAs (one wave)
#define N_PAD   320                   // N padded to 40 n8-fragments
#define D_PITCH 304                   // partials pitch

// ---- packed-B layout (float2 units; float2 = {B[k][n], B[k+4][n]}) ----
#define G_STRIDE   40
#define TIG_STRIDE 322
#define Q_STRIDE   (4 * TIG_STRIDE)   // 1288
#define STAGE_F2   (5 * Q_STRIDE)     // 6440 float2
#define STAGE_B_BYTES (STAGE_F2 * 8)  // 51520 bytes

// ---- GEMM smem layout: 3 pipeline stages ----
#define NSTAGE 3
#define A_PITCH_F  44                 // floats per A row (bank-clean)
#define A_STAGE_BYTES (M_TILE * A_PITCH_F * 4)          // 22528
#define STAGE_TOTAL   (A_STAGE_BYTES + STAGE_B_BYTES)   // 74048
#define SMEM_A(s) ((uint32_t)(s) * STAGE_TOTAL)
#define SMEM_B(s) ((uint32_t)(s) * STAGE_TOTAL + A_STAGE_BYTES)
#define SMEM_TOTAL (NSTAGE * STAGE_TOTAL)               // 222144 <= 227KB limit

// ---------------- device scratch (static: no runtime alloc) ----------------
__device__ __align__(16) float2 g_Bp[(size_t)NKB * STAGE_F2];            // ~64.4 MB
__device__ float g_colsum[D_PITCH];
__device__ __align__(16) float g_part[(size_t)NSPLIT * B_DIM * D_PITCH]; // ~22.4 MB

// ---------------- helpers ----------------
__device__ __forceinline__ uint32_t smem_u32(const void* p) {
    uint32_t a;
    asm("{ .reg .u64 t; cvta.to.shared.u64 t, %1; cvt.u32.u64 %0, t; }" : "=r"(a) : "l"(p));
    return a;
}
__device__ __forceinline__ void cp16(uint32_t dst, const void* src) {
    asm volatile("cp.async.cg.shared.global [%0], [%1], 16;" :: "r"(dst), "l"(src));
}
__device__ __forceinline__ uint32_t f2tf32(float x) {
    uint32_t r;
    asm("cvt.rna.tf32.f32 %0, %1;" : "=r"(r) : "f"(x));
    return r;
}
__device__ __forceinline__ void mma_tf32(float c[4], uint32_t a0, uint32_t a1,
                                         uint32_t a2, uint32_t a3,
                                         uint32_t b0, uint32_t b1) {
    asm volatile(
        "mma.sync.aligned.m16n8k8.row.col.f32.tf32.tf32.f32 "
        "{%0,%1,%2,%3}, {%4,%5,%6,%7}, {%8,%9}, {%0,%1,%2,%3};"
        : "+f"(c[0]), "+f"(c[1]), "+f"(c[2]), "+f"(c[3])
        : "r"(a0), "r"(a1), "r"(a2), "r"(a3), "r"(b0), "r"(b1));
}

// ---------------- kernel 0: zero colsum ----------------
__global__ void zero_colsum_kernel() {
    if (threadIdx.x < D_PITCH) g_colsum[threadIdx.x] = 0.0f;
}

// ---------------- kernel 1: pack W -> g_Bp (tf32-rounded) + colsum ----------------
__global__ void __launch_bounds__(256) prep_kernel(const float* __restrict__ W) {
    __shared__ float raw[K_BLK][D_DIM];   // 48000 B
    const int kb = blockIdx.x;
    const int tid = threadIdx.x;
    const int v0 = kb * K_BLK;

    for (int i = tid; i < K_BLK * 75; i += 256) {
        int r = i / 75, c4 = i % 75;
        float4 v = *reinterpret_cast<const float4*>(W + (size_t)(v0 + r) * D_DIM + c4 * 4);
        *reinterpret_cast<float4*>(&raw[r][c4 * 4]) = v;
    }
    __syncthreads();

    for (int n = tid; n < D_DIM; n += 256) {
        float s = 0.0f;
#pragma unroll
        for (int r = 0; r < K_BLK; r++) s += raw[r][n];
        atomicAdd(&g_colsum[n], s);
    }

    float2* dst = g_Bp + (size_t)kb * STAGE_F2;
    for (int d = tid; d < STAGE_F2; d += 256) {
        int q  = d / Q_STRIDE;    int r1 = d - q * Q_STRIDE;
        int tg = r1 / TIG_STRIDE; int r2 = r1 - tg * TIG_STRIDE;
        int gg = r2 / G_STRIDE;   int f  = r2 - gg * G_STRIDE;
        float2 val = make_float2(0.0f, 0.0f);
        if (gg < 8) {
            int n = gg + 8 * f;
            if (n < D_DIM) {
                val.x = __uint_as_float(f2tf32(raw[q * 8 + tg][n]));
                val.y = __uint_as_float(f2tf32(raw[q * 8 + tg + 4][n]));
            }
        }
        dst[d] = val;
    }
}

// ---------------- kernel 2: split-K tf32 GEMM via mma.sync, 3-stage pipeline ----------------
__device__ __forceinline__ void load_stage(uint32_t sb, const float* __restrict__ A,
                                           int m0, int kb, int buf) {
    const int tid = threadIdx.x;
    const uint32_t a_s = sb + SMEM_A(buf);
    const uint32_t b_s = sb + SMEM_B(buf);
    const int k0 = kb * K_BLK;
#pragma unroll
    for (int it = 0; it < 5; it++) {
        int i = tid + it * 256;
        int r = i / 10, c = i - r * 10;
        cp16(a_s + (uint32_t)(r * (A_PITCH_F * 4) + c * 16),
             A + (size_t)(m0 + r) * V_DIM + k0 + c * 4);
    }
    const char* bsrc = (const char*)(g_Bp + (size_t)kb * STAGE_F2);
#pragma unroll
    for (int it = 0; it < 13; it++) {
        int i = tid + it * 256;
        if (i < STAGE_B_BYTES / 16) cp16(b_s + (uint32_t)(i * 16), bsrc + (size_t)i * 16);
    }
}

__global__ void __launch_bounds__(256, 1)
gemm_kernel(const float* __restrict__ A) {
    extern __shared__ char smem[];
    const uint32_t sb = smem_u32(smem);
    const int tid  = threadIdx.x;
    const int wid  = tid >> 5, lane = tid & 31;
    const int g    = lane >> 2, tig = lane & 3;
    const int wm   = wid & 3;     // 4 M-warps x m32
    const int wn   = wid >> 2;    // 2 N-warps x n160 (20 frags)

    const int m0 = blockIdx.x * M_TILE;
    const int z  = blockIdx.y;
    const int base = NKB / NSPLIT, rem = NKB % NSPLIT;   // 69, 8
    const int t0 = z * base + (z < rem ? z : rem);
    const int T  = base + (z < rem ? 1 : 0);

    float acc[2][20][4];
#pragma unroll
    for (int mf = 0; mf < 2; mf++)
#pragma unroll
        for (int f = 0; f < 20; f++)
#pragma unroll
            for (int j = 0; j < 4; j++) acc[mf][f][j] = 0.0f;

    // prologue: prefetch 2 stages
    load_stage(sb, A, m0, t0, 0);
    asm volatile("cp.async.commit_group;");
    if (T > 1) load_stage(sb, A, m0, t0 + 1, 1);
    asm volatile("cp.async.commit_group;");

    for (int i = 0; i < T; i++) {
        const int buf = i % NSTAGE;
        if (i + 2 < T) {
            load_stage(sb, A, m0, t0 + i + 2, (i + 2) % NSTAGE);
            asm volatile("cp.async.commit_group;");
            asm volatile("cp.async.wait_group 2;");
        } else if (i + 1 < T) {
            asm volatile("cp.async.wait_group 1;");
        } else {
            asm volatile("cp.async.wait_group 0;");
        }
        __syncthreads();

        const uint32_t a_s = sb + SMEM_A(buf);
        const uint32_t b_s = sb + SMEM_B(buf);
#pragma unroll
        for (int q = 0; q < 5; q++) {
            // A fragments: centered by 0.5; raw fp32 bits -> HMMA truncates to tf32.
            uint32_t a[2][4];
#pragma unroll
            for (int mf = 0; mf < 2; mf++) {
                const uint32_t base_addr =
                    a_s + (uint32_t)((wm * 32 + mf * 16 + g) * (A_PITCH_F * 4) +
                                     (q * 8 + tig) * 4);
                float f0, f1, f2, f3;
                asm volatile("ld.shared.f32 %0, [%1];" : "=f"(f0) : "r"(base_addr));
                asm volatile("ld.shared.f32 %0, [%1];" : "=f"(f1) : "r"(base_addr + 8u * A_PITCH_F * 4u));
                asm volatile("ld.shared.f32 %0, [%1];" : "=f"(f2) : "r"(base_addr + 16u));
                asm volatile("ld.shared.f32 %0, [%1];" : "=f"(f3) : "r"(base_addr + 8u * A_PITCH_F * 4u + 16u));
                a[mf][0] = __float_as_uint(f0 - 0.5f);
                a[mf][1] = __float_as_uint(f1 - 0.5f);
                a[mf][2] = __float_as_uint(f2 - 0.5f);
                a[mf][3] = __float_as_uint(f3 - 0.5f);
            }
#pragma unroll
            for (int fp = 0; fp < 10; fp++) {
                const int F0 = wn * 20 + fp * 2;
                const uint32_t baddr =
                    b_s + (uint32_t)((q * Q_STRIDE + tig * TIG_STRIDE + g * G_STRIDE + F0) * 8);
                uint32_t b00, b01, b10, b11;
                asm volatile("ld.shared.v4.b32 {%0,%1,%2,%3}, [%4];"
                             : "=r"(b00), "=r"(b01), "=r"(b10), "=r"(b11)
                             : "r"(baddr));
#pragma unroll
                for (int mf = 0; mf < 2; mf++) {
                    mma_tf32(acc[mf][fp * 2 + 0], a[mf][0], a[mf][1], a[mf][2], a[mf][3], b00, b01);
                    mma_tf32(acc[mf][fp * 2 + 1], a[mf][0], a[mf][1], a[mf][2], a[mf][3], b10, b11);
                }
            }
        }
        __syncthreads();
    }

    // epilogue: write split-K partials (disjoint slices, plain stores)
    float* part = g_part + (size_t)z * B_DIM * D_PITCH;
#pragma unroll
    for (int mf = 0; mf < 2; mf++) {
#pragma unroll
        for (int f = 0; f < 20; f++) {
            const int n = (wn * 20 + f) * 8 + 2 * tig;
            if (n < D_DIM) {
                const int r0 = m0 + wm * 32 + mf * 16 + g;
                *reinterpret_cast<float2*>(part + (size_t)r0 * D_PITCH + n) =
                    make_float2(acc[mf][f][0], acc[mf][f][1]);
                *reinterpret_cast<float2*>(part + (size_t)(r0 + 8) * D_PITCH + n) =
                    make_float2(acc[mf][f][2], acc[mf][f][3]);
            }
        }
    }
}

// ---------------- kernel 3: reduce split-K + colsum + L2 normalize ----------------
__global__ void __launch_bounds__(320) normalize_kernel(float* __restrict__ out) {
    __shared__ float red[10];
    __shared__ float s_inv;
    const int r = blockIdx.x;
    const int tid = threadIdx.x;           // one column per thread (tid < 300 active)
    float v = 0.0f;
    if (tid < D_DIM) {
        v = 0.5f * g_colsum[tid];
#pragma unroll
        for (int zz = 0; zz < NSPLIT; zz++)
            v += g_part[((size_t)zz * B_DIM + r) * D_PITCH + tid];
    }
    float ss = v * v;
#pragma unroll
    for (int o = 16; o; o >>= 1) ss += __shfl_xor_sync(0xffffffffu, ss, o);
    if ((tid & 31) == 0) red[tid >> 5] = ss;
    __syncthreads();
    if (tid < 32) {
        float s = (tid < 10) ? red[tid] : 0.0f;
#pragma unroll
        for (int o = 16; o; o >>= 1) s += __shfl_xor_sync(0xffffffffu, s, o);
        if (tid == 0) s_inv = 1.0f / (sqrtf(s) + EPS);
    }
    __syncthreads();
    if (tid < D_DIM) out[(size_t)r * D_DIM + tid] = v * s_inv;
}

// ---------------- host launch ----------------
extern "C" void kernel_launch(void* const* d_in, const int* in_sizes, int n_in,
                              void* d_out, int out_size) {
    const float* labels = (const float*)d_in[0];
    const float* weight = (const float*)d_in[1];
    if (n_in >= 2 && in_sizes[0] == V_DIM * D_DIM) {  // defensive order swap
        const float* t = labels; labels = weight; weight = t;
    }

    cudaFuncSetAttribute(gemm_kernel, cudaFuncAttributeMaxDynamicSharedMemorySize,
                         SMEM_TOTAL);

    zero_colsum_kernel<<<1, D_PITCH>>>();
    prep_kernel<<<NKB, 256>>>(weight);
    gemm_kernel<<<dim3(M_TILES, NSPLIT), 256, SMEM_TOTAL>>>(labels);
    normalize_kernel<<<B_DIM, 320>>>((float*)d_out);
}

// round 10
// speedup vs baseline: 1.4211x; 1.3624x over previous
#include <cuda_runtime.h>
#include <cuda_fp16.h>
#include <cstdint>
#include <cstddef>

// ---------------- problem constants ----------------
#define B_DIM 1024
#define V_DIM 50000
#define D_DIM 300
#define EPS   1e-7f

#define K_BLK   80                    // K per pipeline stage (5 k16 groups)
#define NKB     (V_DIM / K_BLK)       // 625 stages (exact: 80*625=50000)
#define NSPLIT  18                    // split-K factor
#define M_TILE  128
#define M_TILES (B_DIM / M_TILE)      // 8 -> grid 8 x 18 = 144 CTAs (one wave)
#define D_PITCH 304                   // partials pitch

// ---- packed-B layout (uint2 units; uint2 = {half2(B[k],B[k+1]), half2(B[k+8],B[k+9])}) ----
// per stage: q(k16 group 0..4), tig(k quad), g(n%8), f(n/8) -- same proven geometry as R6/R8
#define G_STRIDE   40
#define TIG_STRIDE 322
#define Q_STRIDE   (4 * TIG_STRIDE)   // 1288
#define STAGE_F2   (5 * Q_STRIDE)     // 6440 uint2
#define STAGE_B_BYTES (STAGE_F2 * 8)  // 51520 bytes

// ---- GEMM smem layout: 2 pipeline stages ----
#define NSTAGE 2
#define A_PITCH_F  84                 // floats per A row (80 + 4 pad)
#define A_STAGE_BYTES (M_TILE * A_PITCH_F * 4)          // 43008
#define STAGE_TOTAL   (A_STAGE_BYTES + STAGE_B_BYTES)   // 94528
#define SMEM_A(s) ((uint32_t)(s) * STAGE_TOTAL)
#define SMEM_B(s) ((uint32_t)(s) * STAGE_TOTAL + A_STAGE_BYTES)
#define SMEM_TOTAL (NSTAGE * STAGE_TOTAL)               // 189056 <= 227KB limit

#define PREP_SMEM (K_BLK * D_DIM * 4)                   // 96000

// ---------------- device scratch (static: no runtime alloc) ----------------
__device__ __align__(16) uint2 g_Bp[(size_t)NKB * STAGE_F2];             // ~32.2 MB
__device__ float g_colsum[D_PITCH];
__device__ __align__(16) float g_part[(size_t)NSPLIT * B_DIM * D_PITCH]; // ~22.4 MB

// ---------------- helpers ----------------
__device__ __forceinline__ uint32_t smem_u32(const void* p) {
    uint32_t a;
    asm("{ .reg .u64 t; cvta.to.shared.u64 t, %1; cvt.u32.u64 %0, t; }" : "=r"(a) : "l"(p));
    return a;
}
__device__ __forceinline__ void cp16(uint32_t dst, const void* src) {
    asm volatile("cp.async.cg.shared.global [%0], [%1], 16;" :: "r"(dst), "l"(src));
}
// pack two centered fp32 -> f16x2 (lo = first k, hi = second k)
__device__ __forceinline__ uint32_t pack_h2(float lo, float hi) {
    uint32_t r;
    asm("cvt.rn.f16x2.f32 %0, %1, %2;" : "=r"(r) : "f"(hi), "f"(lo));
    return r;
}
__device__ __forceinline__ void mma_f16(float c[4], uint32_t a0, uint32_t a1,
                                        uint32_t a2, uint32_t a3,
                                        uint32_t b0, uint32_t b1) {
    asm volatile(
        "mma.sync.aligned.m16n8k16.row.col.f32.f16.f16.f32 "
        "{%0,%1,%2,%3}, {%4,%5,%6,%7}, {%8,%9}, {%0,%1,%2,%3};"
        : "+f"(c[0]), "+f"(c[1]), "+f"(c[2]), "+f"(c[3])
        : "r"(a0), "r"(a1), "r"(a2), "r"(a3), "r"(b0), "r"(b1));
}

// ---------------- kernel 1: pack W -> g_Bp (fp16) + colsum ----------------
// block kb handles W rows [kb*80, kb*80+80): one full GEMM stage.
__global__ void __launch_bounds__(256) prep_kernel(const float* __restrict__ W) {
    extern __shared__ float raw[];        // [80][300]
    const int kb = blockIdx.x;
    const int tid = threadIdx.x;
    const int v0 = kb * K_BLK;

    // 80 rows x 300 floats = 6000 float4 (rows 1200B -> 16B aligned)
    for (int i = tid; i < K_BLK * 75; i += 256) {
        int r = i / 75, c4 = i % 75;
        float4 v = *reinterpret_cast<const float4*>(W + (size_t)(v0 + r) * D_DIM + c4 * 4);
        *reinterpret_cast<float4*>(&raw[r * D_DIM + c4 * 4]) = v;
    }
    __syncthreads();

    // column sums (exact fp32 W), one atomic per column per block (625/addr total)
    for (int n = tid; n < D_DIM; n += 256) {
        float s = 0.0f;
#pragma unroll
        for (int r = 0; r < K_BLK; r++) s += raw[r * D_DIM + n];
        atomicAdd(&g_colsum[n], s);
    }

    // pack stage image
    uint2* dst = g_Bp + (size_t)kb * STAGE_F2;
    for (int d = tid; d < STAGE_F2; d += 256) {
        int q  = d / Q_STRIDE;    int r1 = d - q * Q_STRIDE;
        int tg = r1 / TIG_STRIDE; int r2 = r1 - tg * TIG_STRIDE;
        int gg = r2 / G_STRIDE;   int f  = r2 - gg * G_STRIDE;
        uint2 val = make_uint2(0u, 0u);
        if (gg < 8) {
            int n = gg + 8 * f;
            if (n < D_DIM) {
                int k0 = q * 16 + 2 * tg;
                __half2 lo2 = __floats2half2_rn(raw[k0 * D_DIM + n],
                                                raw[(k0 + 1) * D_DIM + n]);
                __half2 hi2 = __floats2half2_rn(raw[(k0 + 8) * D_DIM + n],
                                                raw[(k0 + 9) * D_DIM + n]);
                val.x = *reinterpret_cast<uint32_t*>(&lo2);
                val.y = *reinterpret_cast<uint32_t*>(&hi2);
            }
        }
        dst[d] = val;
    }
}

// ---------------- kernel 2: split-K fp16 GEMM via mma.sync m16n8k16 ----------------
__device__ __forceinline__ void load_stage(uint32_t sb, const float* __restrict__ A,
                                           int m0, int kb, int buf) {
    const int tid = threadIdx.x;
    const uint32_t a_s = sb + SMEM_A(buf);
    const uint32_t b_s = sb + SMEM_B(buf);
    const int k0 = kb * K_BLK;
    // A: 128 rows x 320B = 2560 x 16B chunks (exactly 10 per thread)
#pragma unroll
    for (int it = 0; it < 10; it++) {
        int i = tid + it * 256;
        int r = i / 20, c = i - r * 20;
        cp16(a_s + (uint32_t)(r * (A_PITCH_F * 4) + c * 16),
             A + (size_t)(m0 + r) * V_DIM + k0 + c * 4);
    }
    // B: contiguous stage image, 3220 x 16B chunks
    const char* bsrc = (const char*)(g_Bp + (size_t)kb * STAGE_F2);
#pragma unroll
    for (int it = 0; it < 13; it++) {
        int i = tid + it * 256;
        if (i < STAGE_B_BYTES / 16) cp16(b_s + (uint32_t)(i * 16), bsrc + (size_t)i * 16);
    }
}

__global__ void __launch_bounds__(256, 1)
gemm_kernel(const float* __restrict__ A) {
    extern __shared__ char smem[];
    const uint32_t sb = smem_u32(smem);
    const int tid  = threadIdx.x;
    const int wid  = tid >> 5, lane = tid & 31;
    const int g    = lane >> 2, tig = lane & 3;
    const int wm   = wid & 3;     // 4 M-warps x m32
    const int wn   = wid >> 2;    // 2 N-warps (wn0: frags 0-19, wn1: frags 20-37 real)

    const int m0 = blockIdx.x * M_TILE;
    const int z  = blockIdx.y;
    const int base = NKB / NSPLIT, rem = NKB % NSPLIT;   // 34, 13
    const int t0 = z * base + (z < rem ? z : rem);
    const int T  = base + (z < rem ? 1 : 0);

    float acc[2][20][4];
#pragma unroll
    for (int mf = 0; mf < 2; mf++)
#pragma unroll
        for (int f = 0; f < 20; f++)
#pragma unroll
            for (int j = 0; j < 4; j++) acc[mf][f][j] = 0.0f;

    load_stage(sb, A, m0, t0, 0);
    asm volatile("cp.async.commit_group;");

    for (int i = 0; i < T; i++) {
        const int buf = i & 1;
        if (i + 1 < T) {
            load_stage(sb, A, m0, t0 + i + 1, buf ^ 1);
            asm volatile("cp.async.commit_group;");
            asm volatile("cp.async.wait_group 1;");
        } else {
            asm volatile("cp.async.wait_group 0;");
        }
        __syncthreads();

        const uint32_t a_s = sb + SMEM_A(buf);
        const uint32_t b_s = sb + SMEM_B(buf);
#pragma unroll
        for (int q = 0; q < 5; q++) {
            // A fragments: centered by 0.5, converted to f16x2 in-register.
            uint32_t a[2][4];
#pragma unroll
            for (int mf = 0; mf < 2; mf++) {
                const int r0 = wm * 32 + mf * 16 + g;
                const uint32_t a0addr =
                    a_s + (uint32_t)(r0 * (A_PITCH_F * 4) + (q * 16 + 2 * tig) * 4);
                const uint32_t a1addr = a0addr + 8u * A_PITCH_F * 4u;
                float f0, f1, f2, f3, f4, f5, f6, f7;
                asm volatile("ld.shared.v2.f32 {%0,%1}, [%2];" : "=f"(f0), "=f"(f1) : "r"(a0addr));
                asm volatile("ld.shared.v2.f32 {%0,%1}, [%2];" : "=f"(f2), "=f"(f3) : "r"(a1addr));
                asm volatile("ld.shared.v2.f32 {%0,%1}, [%2];" : "=f"(f4), "=f"(f5) : "r"(a0addr + 32u));
                asm volatile("ld.shared.v2.f32 {%0,%1}, [%2];" : "=f"(f6), "=f"(f7) : "r"(a1addr + 32u));
                a[mf][0] = pack_h2(f0 - 0.5f, f1 - 0.5f);
                a[mf][1] = pack_h2(f2 - 0.5f, f3 - 0.5f);
                a[mf][2] = pack_h2(f4 - 0.5f, f5 - 0.5f);
                a[mf][3] = pack_h2(f6 - 0.5f, f7 - 0.5f);
            }
#pragma unroll
            for (int fp = 0; fp < 10; fp++) {
                if (wn == 1 && fp == 9) break;   // frags 38,39 are zero-pad: skip
                const int F0 = wn * 20 + fp * 2;
                const uint32_t baddr =
                    b_s + (uint32_t)((q * Q_STRIDE + tig * TIG_STRIDE + g * G_STRIDE + F0) * 8);
                uint32_t b00, b01, b10, b11;
                asm volatile("ld.shared.v4.b32 {%0,%1,%2,%3}, [%4];"
                             : "=r"(b00), "=r"(b01), "=r"(b10), "=r"(b11)
                             : "r"(baddr));
#pragma unroll
                for (int mf = 0; mf < 2; mf++) {
                    mma_f16(acc[mf][fp * 2 + 0], a[mf][0], a[mf][1], a[mf][2], a[mf][3], b00, b01);
                    mma_f16(acc[mf][fp * 2 + 1], a[mf][0], a[mf][1], a[mf][2], a[mf][3], b10, b11);
                }
            }
        }
        __syncthreads();
    }

    // epilogue: write split-K partials (disjoint slices, plain stores)
    float* part = g_part + (size_t)z * B_DIM * D_PITCH;
#pragma unroll
    for (int mf = 0; mf < 2; mf++) {
#pragma unroll
        for (int f = 0; f < 20; f++) {
            const int n = (wn * 20 + f) * 8 + 2 * tig;
            if (n < D_DIM) {
                const int r0 = m0 + wm * 32 + mf * 16 + g;
                *reinterpret_cast<float2*>(part + (size_t)r0 * D_PITCH + n) =
                    make_float2(acc[mf][f][0], acc[mf][f][1]);
                *reinterpret_cast<float2*>(part + (size_t)(r0 + 8) * D_PITCH + n) =
                    make_float2(acc[mf][f][2], acc[mf][f][3]);
            }
        }
    }
}

// ---------------- kernel 3: reduce split-K + colsum + L2 normalize ----------------
__global__ void __launch_bounds__(320) normalize_kernel(float* __restrict__ out) {
    __shared__ float red[10];
    __shared__ float s_inv;
    const int r = blockIdx.x;
    const int tid = threadIdx.x;           // one column per thread (tid < 300 active)
    float v = 0.0f;
    if (tid < D_DIM) {
        v = 0.5f * g_colsum[tid];
#pragma unroll
        for (int zz = 0; zz < NSPLIT; zz++)
            v += g_part[((size_t)zz * B_DIM + r) * D_PITCH + tid];
    }
    float ss = v * v;
#pragma unroll
    for (int o = 16; o; o >>= 1) ss += __shfl_xor_sync(0xffffffffu, ss, o);
    if ((tid & 31) == 0) red[tid >> 5] = ss;
    __syncthreads();
    if (tid < 32) {
        float s = (tid < 10) ? red[tid] : 0.0f;
#pragma unroll
        for (int o = 16; o; o >>= 1) s += __shfl_xor_sync(0xffffffffu, s, o);
        if (tid == 0) s_inv = 1.0f / (sqrtf(s) + EPS);
    }
    __syncthreads();
    if (tid < D_DIM) out[(size_t)r * D_DIM + tid] = v * s_inv;
}

// ---------------- host launch ----------------
extern "C" void kernel_launch(void* const* d_in, const int* in_sizes, int n_in,
                              void* d_out, int out_size) {
    const float* labels = (const float*)d_in[0];
    const float* weight = (const float*)d_in[1];
    if (n_in >= 2 && in_sizes[0] == V_DIM * D_DIM) {  // defensive order swap
        const float* t = labels; labels = weight; weight = t;
    }

    cudaFuncSetAttribute(gemm_kernel, cudaFuncAttributeMaxDynamicSharedMemorySize,
                         SMEM_TOTAL);
    cudaFuncSetAttribute(prep_kernel, cudaFuncAttributeMaxDynamicSharedMemorySize,
                         PREP_SMEM);

    void* colsum_ptr = nullptr;
    cudaGetSymbolAddress(&colsum_ptr, g_colsum);
    cudaMemsetAsync(colsum_ptr, 0, D_PITCH * sizeof(float));

    prep_kernel<<<NKB, 256, PREP_SMEM>>>(weight);
    gemm_kernel<<<dim3(M_TILES, NSPLIT), 256, SMEM_TOTAL>>>(labels);
    normalize_kernel<<<B_DIM, 320>>>((float*)d_out);
}

// round 11
// speedup vs baseline: 1.4977x; 1.0539x over previous
#include <cuda_runtime.h>
#include <cuda_fp16.h>
#include <cstdint>
#include <cstddef>

// ---------------- problem constants ----------------
#define B_DIM 1024
#define V_DIM 50000
#define D_DIM 300
#define EPS   1e-7f

#define K_BLK   80                    // K per pipeline stage (5 k16 groups)
#define NKB     (V_DIM / K_BLK)       // 625 stages (exact: 80*625=50000)
#define NSPLIT  18                    // split-K factor
#define M_TILE  128
#define M_TILES (B_DIM / M_TILE)      // 8 -> grid 8 x 18 = 144 CTAs (one wave)
#define D_PITCH 304                   // partials pitch

// ---- packed-B layout (uint2 units; uint2 = {half2(B[k],B[k+1]), half2(B[k+8],B[k+9])}) ----
// per stage: q(k16 group 0..4), tig(k quad), g(n%8), f(n/8)
#define G_STRIDE   40
#define TIG_STRIDE 322
#define Q_STRIDE   (4 * TIG_STRIDE)   // 1288
#define STAGE_F2   (5 * Q_STRIDE)     // 6440 uint2
#define STAGE_B_BYTES (STAGE_F2 * 8)  // 51520 bytes

// ---- GEMM smem layout: 2 pipeline stages ----
#define NSTAGE 2
#define A_PITCH_F  84                 // floats per A row (80 + 4 pad)
#define A_STAGE_BYTES (M_TILE * A_PITCH_F * 4)          // 43008
#define STAGE_TOTAL   (A_STAGE_BYTES + STAGE_B_BYTES)   // 94528
#define SMEM_A(s) ((uint32_t)(s) * STAGE_TOTAL)
#define SMEM_B(s) ((uint32_t)(s) * STAGE_TOTAL + A_STAGE_BYTES)
#define SMEM_TOTAL (NSTAGE * STAGE_TOTAL)               // 189056 <= 227KB limit

// ---------------- device scratch (static: no runtime alloc) ----------------
__device__ __align__(16) uint2 g_Bp[(size_t)NKB * STAGE_F2];             // ~32.2 MB
__device__ float g_colsum[D_PITCH];
__device__ __align__(16) float g_part[(size_t)NSPLIT * B_DIM * D_PITCH]; // ~22.4 MB

// ---------------- helpers ----------------
__device__ __forceinline__ uint32_t smem_u32(const void* p) {
    uint32_t a;
    asm("{ .reg .u64 t; cvta.to.shared.u64 t, %1; cvt.u32.u64 %0, t; }" : "=r"(a) : "l"(p));
    return a;
}
__device__ __forceinline__ void cp16(uint32_t dst, const void* src) {
    asm volatile("cp.async.cg.shared.global [%0], [%1], 16;" :: "r"(dst), "l"(src));
}
// pack two centered fp32 -> f16x2 (lo = first k, hi = second k)
__device__ __forceinline__ uint32_t pack_h2(float lo, float hi) {
    uint32_t r;
    asm("cvt.rn.f16x2.f32 %0, %1, %2;" : "=r"(r) : "f"(hi), "f"(lo));
    return r;
}
__device__ __forceinline__ void mma_f16(float c[4], uint32_t a0, uint32_t a1,
                                        uint32_t a2, uint32_t a3,
                                        uint32_t b0, uint32_t b1) {
    asm volatile(
        "mma.sync.aligned.m16n8k16.row.col.f32.f16.f16.f32 "
        "{%0,%1,%2,%3}, {%4,%5,%6,%7}, {%8,%9}, {%0,%1,%2,%3};"
        : "+f"(c[0]), "+f"(c[1]), "+f"(c[2]), "+f"(c[3])
        : "r"(a0), "r"(a1), "r"(a2), "r"(a3), "r"(b0), "r"(b1));
}

// ---------------- kernel 1: pack W -> g_Bp (fp16) + colsum ----------------
// block (kb, q) handles W rows [kb*80 + q*16, +16): one q-segment of one stage.
// 19.2KB static smem -> 8 CTAs/SM; one int-div per thread; coalesced 8B stores.
__global__ void __launch_bounds__(256) prep_kernel(const float* __restrict__ W) {
    __shared__ float raw[16][D_DIM];      // 19200 B
    const int kb = blockIdx.x;
    const int q  = blockIdx.y;
    const int tid = threadIdx.x;
    const int v0 = kb * K_BLK + q * 16;

    // load 16 rows x 300 floats = 1200 float4 (rows 1200B -> 16B aligned)
    for (int i = tid; i < 16 * 75; i += 256) {
        int r = i / 75, c4 = i % 75;
        float4 v = *reinterpret_cast<const float4*>(W + (size_t)(v0 + r) * D_DIM + c4 * 4);
        *reinterpret_cast<float4*>(&raw[r][c4 * 4]) = v;
    }
    __syncthreads();

    // partial column sums for these 16 rows (3125 atomics/address total: cheap)
    for (int n = tid; n < D_DIM; n += 256) {
        float s = 0.0f;
#pragma unroll
        for (int r = 0; r < 16; r++) s += raw[r][n];
        atomicAdd(&g_colsum[n], s);
    }

    // pack segment q: dst[tg*TIG_STRIDE + d2], d2 in [0, TIG_STRIDE)
    uint2* dst = g_Bp + (size_t)kb * STAGE_F2 + (size_t)q * Q_STRIDE;
    for (int d2 = tid; d2 < TIG_STRIDE; d2 += 256) {
        const int gg = d2 / G_STRIDE;
        const int f  = d2 - gg * G_STRIDE;
        const int n  = gg + 8 * f;
        const bool valid = (gg < 8) && (n < D_DIM);
#pragma unroll
        for (int tg = 0; tg < 4; tg++) {
            uint2 val = make_uint2(0u, 0u);
            if (valid) {
                const int k0 = 2 * tg;
                __half2 lo2 = __floats2half2_rn(raw[k0][n],     raw[k0 + 1][n]);
                __half2 hi2 = __floats2half2_rn(raw[k0 + 8][n], raw[k0 + 9][n]);
                val.x = *reinterpret_cast<uint32_t*>(&lo2);
                val.y = *reinterpret_cast<uint32_t*>(&hi2);
            }
            dst[tg * TIG_STRIDE + d2] = val;   // contiguous across tid
        }
    }
}

// ---------------- kernel 2: split-K fp16 GEMM via mma.sync m16n8k16 ----------------
__device__ __forceinline__ void load_stage(uint32_t sb, const float* __restrict__ A,
                                           int m0, int kb, int buf) {
    const int tid = threadIdx.x;
    const uint32_t a_s = sb + SMEM_A(buf);
    const uint32_t b_s = sb + SMEM_B(buf);
    const int k0 = kb * K_BLK;
    // A: 128 rows x 320B = 2560 x 16B chunks (exactly 10 per thread)
#pragma unroll
    for (int it = 0; it < 10; it++) {
        int i = tid + it * 256;
        int r = i / 20, c = i - r * 20;
        cp16(a_s + (uint32_t)(r * (A_PITCH_F * 4) + c * 16),
             A + (size_t)(m0 + r) * V_DIM + k0 + c * 4);
    }
    // B: contiguous stage image, 3220 x 16B chunks
    const char* bsrc = (const char*)(g_Bp + (size_t)kb * STAGE_F2);
#pragma unroll
    for (int it = 0; it < 13; it++) {
        int i = tid + it * 256;
        if (i < STAGE_B_BYTES / 16) cp16(b_s + (uint32_t)(i * 16), bsrc + (size_t)i * 16);
    }
}

__global__ void __launch_bounds__(256, 1)
gemm_kernel(const float* __restrict__ A) {
    extern __shared__ char smem[];
    const uint32_t sb = smem_u32(smem);
    const int tid  = threadIdx.x;
    const int wid  = tid >> 5, lane = tid & 31;
    const int g    = lane >> 2, tig = lane & 3;
    const int wm   = wid & 3;     // 4 M-warps x m32
    const int wn   = wid >> 2;    // 2 N-warps (wn0: frags 0-19, wn1: frags 20-37 real)

    const int m0 = blockIdx.x * M_TILE;
    const int z  = blockIdx.y;
    const int base = NKB / NSPLIT, rem = NKB % NSPLIT;   // 34, 13
    const int t0 = z * base + (z < rem ? z : rem);
    const int T  = base + (z < rem ? 1 : 0);

    float acc[2][20][4];
#pragma unroll
    for (int mf = 0; mf < 2; mf++)
#pragma unroll
        for (int f = 0; f < 20; f++)
#pragma unroll
            for (int j = 0; j < 4; j++) acc[mf][f][j] = 0.0f;

    load_stage(sb, A, m0, t0, 0);
    asm volatile("cp.async.commit_group;");

    for (int i = 0; i < T; i++) {
        const int buf = i & 1;
        if (i + 1 < T) {
            load_stage(sb, A, m0, t0 + i + 1, buf ^ 1);
            asm volatile("cp.async.commit_group;");
            asm volatile("cp.async.wait_group 1;");
        } else {
            asm volatile("cp.async.wait_group 0;");
        }
        __syncthreads();

        const uint32_t a_s = sb + SMEM_A(buf);
        const uint32_t b_s = sb + SMEM_B(buf);
#pragma unroll
        for (int q = 0; q < 5; q++) {
            // A fragments: centered by 0.5, converted to f16x2 in-register.
            uint32_t a[2][4];
#pragma unroll
            for (int mf = 0; mf < 2; mf++) {
                const int r0 = wm * 32 + mf * 16 + g;
                const uint32_t a0addr =
                    a_s + (uint32_t)(r0 * (A_PITCH_F * 4) + (q * 16 + 2 * tig) * 4);
                const uint32_t a1addr = a0addr + 8u * A_PITCH_F * 4u;
                float f0, f1, f2, f3, f4, f5, f6, f7;
                asm volatile("ld.shared.v2.f32 {%0,%1}, [%2];" : "=f"(f0), "=f"(f1) : "r"(a0addr));
                asm volatile("ld.shared.v2.f32 {%0,%1}, [%2];" : "=f"(f2), "=f"(f3) : "r"(a1addr));
                asm volatile("ld.shared.v2.f32 {%0,%1}, [%2];" : "=f"(f4), "=f"(f5) : "r"(a0addr + 32u));
                asm volatile("ld.shared.v2.f32 {%0,%1}, [%2];" : "=f"(f6), "=f"(f7) : "r"(a1addr + 32u));
                a[mf][0] = pack_h2(f0 - 0.5f, f1 - 0.5f);
                a[mf][1] = pack_h2(f2 - 0.5f, f3 - 0.5f);
                a[mf][2] = pack_h2(f4 - 0.5f, f5 - 0.5f);
                a[mf][3] = pack_h2(f6 - 0.5f, f7 - 0.5f);
            }
#pragma unroll
            for (int fp = 0; fp < 10; fp++) {
                if (wn == 1 && fp == 9) break;   // frags 38,39 are zero-pad: skip
                const int F0 = wn * 20 + fp * 2;
                const uint32_t baddr =
                    b_s + (uint32_t)((q * Q_STRIDE + tig * TIG_STRIDE + g * G_STRIDE + F0) * 8);
                uint32_t b00, b01, b10, b11;
                asm volatile("ld.shared.v4.b32 {%0,%1,%2,%3}, [%4];"
                             : "=r"(b00), "=r"(b01), "=r"(b10), "=r"(b11)
                             : "r"(baddr));
#pragma unroll
                for (int mf = 0; mf < 2; mf++) {
                    mma_f16(acc[mf][fp * 2 + 0], a[mf][0], a[mf][1], a[mf][2], a[mf][3], b00, b01);
                    mma_f16(acc[mf][fp * 2 + 1], a[mf][0], a[mf][1], a[mf][2], a[mf][3], b10, b11);
                }
            }
        }
        __syncthreads();
    }

    // epilogue: write split-K partials (disjoint slices, plain stores)
    float* part = g_part + (size_t)z * B_DIM * D_PITCH;
#pragma unroll
    for (int mf = 0; mf < 2; mf++) {
#pragma unroll
        for (int f = 0; f < 20; f++) {
            const int n = (wn * 20 + f) * 8 + 2 * tig;
            if (n < D_DIM) {
                const int r0 = m0 + wm * 32 + mf * 16 + g;
                *reinterpret_cast<float2*>(part + (size_t)r0 * D_PITCH + n) =
                    make_float2(acc[mf][f][0], acc[mf][f][1]);
                *reinterpret_cast<float2*>(part + (size_t)(r0 + 8) * D_PITCH + n) =
                    make_float2(acc[mf][f][2], acc[mf][f][3]);
            }
        }
    }
}

// ---------------- kernel 3: reduce split-K + colsum + L2 normalize ----------------
__global__ void __launch_bounds__(320) normalize_kernel(float* __restrict__ out) {
    __shared__ float red[10];
    __shared__ float s_inv;
    const int r = blockIdx.x;
    const int tid = threadIdx.x;           // one column per thread (tid < 300 active)
    float v = 0.0f;
    if (tid < D_DIM) {
        v = 0.5f * g_colsum[tid];
#pragma unroll
        for (int zz = 0; zz < NSPLIT; zz++)
            v += g_part[((size_t)zz * B_DIM + r) * D_PITCH + tid];
    }
    float ss = v * v;
#pragma unroll
    for (int o = 16; o; o >>= 1) ss += __shfl_xor_sync(0xffffffffu, ss, o);
    if ((tid & 31) == 0) red[tid >> 5] = ss;
    __syncthreads();
    if (tid < 32) {
        float s = (tid < 10) ? red[tid] : 0.0f;
#pragma unroll
        for (int o = 16; o; o >>= 1) s += __shfl_xor_sync(0xffffffffu, s, o);
        if (tid == 0) s_inv = 1.0f / (sqrtf(s) + EPS);
    }
    __syncthreads();
    if (tid < D_DIM) out[(size_t)r * D_DIM + tid] = v * s_inv;
}

// ---------------- host launch ----------------
extern "C" void kernel_launch(void* const* d_in, const int* in_sizes, int n_in,
                              void* d_out, int out_size) {
    const float* labels = (const float*)d_in[0];
    const float* weight = (const float*)d_in[1];
    if (n_in >= 2 && in_sizes[0] == V_DIM * D_DIM) {  // defensive order swap
        const float* t = labels; labels = weight; weight = t;
    }

    cudaFuncSetAttribute(gemm_kernel, cudaFuncAttributeMaxDynamicSharedMemorySize,
                         SMEM_TOTAL);

    void* colsum_ptr = nullptr;
    cudaGetSymbolAddress(&colsum_ptr, g_colsum);
    cudaMemsetAsync(colsum_ptr, 0, D_PITCH * sizeof(float));

    prep_kernel<<<dim3(NKB, 5), 256>>>(weight);
    gemm_kernel<<<dim3(M_TILES, NSPLIT), 256, SMEM_TOTAL>>>(labels);
    normalize_kernel<<<B_DIM, 320>>>((float*)d_out);
}

// round 15
// speedup vs baseline: 1.5033x; 1.0037x over previous
#include <cuda_runtime.h>
#include <cuda_fp16.h>
#include <cstdint>
#include <cstddef>

// ---------------- problem constants ----------------
#define B_DIM 1024
#define V_DIM 50000
#define D_DIM 300
#define EPS   1e-7f

#define K_BLK   80                    // K per pipeline stage (5 k16 groups)
#define NKB     (V_DIM / K_BLK)       // 625 stages (exact: 80*625=50000)
#define NSPLIT  18                    // split-K factor
#define M_TILE  128
#define M_TILES (B_DIM / M_TILE)      // 8 -> grid 8 x 18 = 144 CTAs (one wave)
#define D_PITCH 304                   // partials pitch

// ---- packed-B layout (uint2 units; uint2 = {half2(B[k],B[k+1]), half2(B[k+8],B[k+9])}) ----
// per stage: q(k16 group 0..4), tig(k quad), g(n%8), f(n/8)
#define G_STRIDE   40
#define TIG_STRIDE 322
#define Q_STRIDE   (4 * TIG_STRIDE)   // 1288
#define STAGE_F2   (5 * Q_STRIDE)     // 6440 uint2
#define STAGE_B_BYTES (STAGE_F2 * 8)  // 51520 bytes

// ---- GEMM smem layout: 2 pipeline stages ----
#define NSTAGE 2
#define A_PITCH_F  84                 // floats per A row (80 + 4 pad)
#define A_STAGE_BYTES (M_TILE * A_PITCH_F * 4)          // 43008
#define STAGE_TOTAL   (A_STAGE_BYTES + STAGE_B_BYTES)   // 94528
#define SMEM_A(s) ((uint32_t)(s) * STAGE_TOTAL)
#define SMEM_B(s) ((uint32_t)(s) * STAGE_TOTAL + A_STAGE_BYTES)
#define SMEM_TOTAL (NSTAGE * STAGE_TOTAL)               // 189056 <= 227KB limit

// ---------------- device scratch (static: no runtime alloc) ----------------
__device__ __align__(16) uint2 g_Bp[(size_t)NKB * STAGE_F2];             // ~32.2 MB
__device__ float g_colsum[D_PITCH];
__device__ __align__(16) float g_part[(size_t)NSPLIT * B_DIM * D_PITCH]; // ~22.4 MB

// ---------------- helpers ----------------
__device__ __forceinline__ uint32_t smem_u32(const void* p) {
    uint32_t a;
    asm("{ .reg .u64 t; cvta.to.shared.u64 t, %1; cvt.u32.u64 %0, t; }" : "=r"(a) : "l"(p));
    return a;
}
__device__ __forceinline__ void cp16(uint32_t dst, const void* src) {
    asm volatile("cp.async.cg.shared.global [%0], [%1], 16;" :: "r"(dst), "l"(src));
}
// pack two centered fp32 -> f16x2 (lo = first k, hi = second k)
__device__ __forceinline__ uint32_t pack_h2(float lo, float hi) {
    uint32_t r;
    asm("cvt.rn.f16x2.f32 %0, %1, %2;" : "=r"(r) : "f"(hi), "f"(lo));
    return r;
}
__device__ __forceinline__ void mma_f16(float c[4], uint32_t a0, uint32_t a1,
                                        uint32_t a2, uint32_t a3,
                                        uint32_t b0, uint32_t b1) {
    asm volatile(
        "mma.sync.aligned.m16n8k16.row.col.f32.f16.f16.f32 "
        "{%0,%1,%2,%3}, {%4,%5,%6,%7}, {%8,%9}, {%0,%1,%2,%3};"
        : "+f"(c[0]), "+f"(c[1]), "+f"(c[2]), "+f"(c[3])
        : "r"(a0), "r"(a1), "r"(a2), "r"(a3), "r"(b0), "r"(b1));
}

// ---------------- kernel 1: pack W -> g_Bp (fp16) + colsum ----------------
// block (kb, q) handles W rows [kb*80 + q*16, +16).
// Lane map: gg = lane>>2, f = 4*it + (lane&3)  =>  n = gg + 8*(lane&3) + 32*it
//   -> n mod 32 distinct across the warp: conflict-free smem reads.
__global__ void __launch_bounds__(256) prep_kernel(const float* __restrict__ W) {
    __shared__ float raw[16][D_DIM];      // 19200 B
    const int kb = blockIdx.x;
    const int q  = blockIdx.y;
    const int tid = threadIdx.x;
    const int wid = tid >> 5, lane = tid & 31;
    const int v0 = kb * K_BLK + q * 16;

    // load 16 rows x 300 floats = 1200 float4 (rows 1200B -> 16B aligned)
    for (int i = tid; i < 16 * 75; i += 256) {
        int r = i / 75, c4 = i % 75;
        float4 v = *reinterpret_cast<const float4*>(W + (size_t)(v0 + r) * D_DIM + c4 * 4);
        *reinterpret_cast<float4*>(&raw[r][c4 * 4]) = v;
    }
    __syncthreads();

    // partial column sums for these 16 rows (conflict-free: n consecutive per lane)
    for (int n = tid; n < D_DIM; n += 256) {
        float s = 0.0f;
#pragma unroll
        for (int r = 0; r < 16; r++) s += raw[r][n];
        atomicAdd(&g_colsum[n], s);
    }

    // pack segment q (conflict-free reads, 32B-sector-complete writes)
    uint2* dst = g_Bp + (size_t)kb * STAGE_F2 + (size_t)q * Q_STRIDE;
    const int gg = lane >> 2;
    const int fl = lane & 3;
    for (int it = wid; it < 10; it += 8) {
        const int f = it * 4 + fl;           // 0..39
        const int n = gg + 8 * f;            // 0..319
        const int d2 = gg * G_STRIDE + f;
        if (n < D_DIM) {
#pragma unroll
            for (int tg = 0; tg < 4; tg++) {
                const int k0 = 2 * tg;
                uint2 val;
                val.x = pack_h2(raw[k0][n],     raw[k0 + 1][n]);
                val.y = pack_h2(raw[k0 + 8][n], raw[k0 + 9][n]);
                dst[tg * TIG_STRIDE + d2] = val;
            }
        } else {
#pragma unroll
            for (int tg = 0; tg < 4; tg++)
                dst[tg * TIG_STRIDE + d2] = make_uint2(0u, 0u);
        }
    }
    // pad entries d2 = 320, 321 per tig
    if (tid < 8) {
        const int tg = tid >> 1, e = tid & 1;
        dst[tg * TIG_STRIDE + 320 + e] = make_uint2(0u, 0u);
    }
}

// ---------------- kernel 2: split-K fp16 GEMM via mma.sync m16n8k16 ----------------
__device__ __forceinline__ void load_stage(uint32_t sb, const float* __restrict__ A,
                                           int m0, int kb, int buf) {
    const int tid = threadIdx.x;
    const uint32_t a_s = sb + SMEM_A(buf);
    const uint32_t b_s = sb + SMEM_B(buf);
    const int k0 = kb * K_BLK;
    // A: 128 rows x 320B = 2560 x 16B chunks (exactly 10 per thread)
#pragma unroll
    for (int it = 0; it < 10; it++) {
        int i = tid + it * 256;
        int r = i / 20, c = i - r * 20;
        cp16(a_s + (uint32_t)(r * (A_PITCH_F * 4) + c * 16),
             A + (size_t)(m0 + r) * V_DIM + k0 + c * 4);
    }
    // B: contiguous stage image, 3220 x 16B chunks
    const char* bsrc = (const char*)(g_Bp + (size_t)kb * STAGE_F2);
#pragma unroll
    for (int it = 0; it < 13; it++) {
        int i = tid + it * 256;
        if (i < STAGE_B_BYTES / 16) cp16(b_s + (uint32_t)(i * 16), bsrc + (size_t)i * 16);
    }
}

__global__ void __launch_bounds__(256, 1)
gemm_kernel(const float* __restrict__ A) {
    extern __shared__ char smem[];
    const uint32_t sb = smem_u32(smem);
    const int tid  = threadIdx.x;
    const int wid  = tid >> 5, lane = tid & 31;
    const int g    = lane >> 2, tig = lane & 3;
    const int wm   = wid & 3;     // 4 M-warps x m32
    const int wn   = wid >> 2;    // 2 N-warps (wn0: frags 0-19, wn1: frags 20-37 real)

    const int m0 = blockIdx.x * M_TILE;
    const int z  = blockIdx.y;
    const int base = NKB / NSPLIT, rem = NKB % NSPLIT;   // 34, 13
    const int t0 = z * base + (z < rem ? z : rem);
    const int T  = base + (z < rem ? 1 : 0);

    float acc[2][20][4];
#pragma unroll
    for (int mf = 0; mf < 2; mf++)
#pragma unroll
        for (int f = 0; f < 20; f++)
#pragma unroll
            for (int j = 0; j < 4; j++) acc[mf][f][j] = 0.0f;

    load_stage(sb, A, m0, t0, 0);
    asm volatile("cp.async.commit_group;");

    for (int i = 0; i < T; i++) {
        const int buf = i & 1;
        if (i + 1 < T) {
            load_stage(sb, A, m0, t0 + i + 1, buf ^ 1);
            asm volatile("cp.async.commit_group;");
            asm volatile("cp.async.wait_group 1;");
        } else {
            asm volatile("cp.async.wait_group 0;");
        }
        __syncthreads();

        const uint32_t a_s = sb + SMEM_A(buf);
        const uint32_t b_s = sb + SMEM_B(buf);
#pragma unroll
        for (int q = 0; q < 5; q++) {
            // A fragments: centered by 0.5, converted to f16x2 in-register.
            uint32_t a[2][4];
#pragma unroll
            for (int mf = 0; mf < 2; mf++) {
                const int r0 = wm * 32 + mf * 16 + g;
                const uint32_t a0addr =
                    a_s + (uint32_t)(r0 * (A_PITCH_F * 4) + (q * 16 + 2 * tig) * 4);
                const uint32_t a1addr = a0addr + 8u * A_PITCH_F * 4u;
                float f0, f1, f2, f3, f4, f5, f6, f7;
                asm volatile("ld.shared.v2.f32 {%0,%1}, [%2];" : "=f"(f0), "=f"(f1) : "r"(a0addr));
                asm volatile("ld.shared.v2.f32 {%0,%1}, [%2];" : "=f"(f2), "=f"(f3) : "r"(a1addr));
                asm volatile("ld.shared.v2.f32 {%0,%1}, [%2];" : "=f"(f4), "=f"(f5) : "r"(a0addr + 32u));
                asm volatile("ld.shared.v2.f32 {%0,%1}, [%2];" : "=f"(f6), "=f"(f7) : "r"(a1addr + 32u));
                a[mf][0] = pack_h2(f0 - 0.5f, f1 - 0.5f);
                a[mf][1] = pack_h2(f2 - 0.5f, f3 - 0.5f);
                a[mf][2] = pack_h2(f4 - 0.5f, f5 - 0.5f);
                a[mf][3] = pack_h2(f6 - 0.5f, f7 - 0.5f);
            }
#pragma unroll
            for (int fp = 0; fp < 10; fp++) {
                if (wn == 1 && fp == 9) break;   // frags 38,39 are zero-pad: skip
                const int F0 = wn * 20 + fp * 2;
                const uint32_t baddr =
                    b_s + (uint32_t)((q * Q_STRIDE + tig * TIG_STRIDE + g * G_STRIDE + F0) * 8);
                uint32_t b00, b01, b10, b11;
                asm volatile("ld.shared.v4.b32 {%0,%1,%2,%3}, [%4];"
                             : "=r"(b00), "=r"(b01), "=r"(b10), "=r"(b11)
                             : "r"(baddr));
#pragma unroll
                for (int mf = 0; mf < 2; mf++) {
                    mma_f16(acc[mf][fp * 2 + 0], a[mf][0], a[mf][1], a[mf][2], a[mf][3], b00, b01);
                    mma_f16(acc[mf][fp * 2 + 1], a[mf][0], a[mf][1], a[mf][2], a[mf][3], b10, b11);
                }
            }
        }
        __syncthreads();
    }

    // epilogue: write split-K partials (disjoint slices, plain stores)
    float* part = g_part + (size_t)z * B_DIM * D_PITCH;
#pragma unroll
    for (int mf = 0; mf < 2; mf++) {
#pragma unroll
        for (int f = 0; f < 20; f++) {
            const int n = (wn * 20 + f) * 8 + 2 * tig;
            if (n < D_DIM) {
                const int r0 = m0 + wm * 32 + mf * 16 + g;
                *reinterpret_cast<float2*>(part + (size_t)r0 * D_PITCH + n) =
                    make_float2(acc[mf][f][0], acc[mf][f][1]);
                *reinterpret_cast<float2*>(part + (size_t)(r0 + 8) * D_PITCH + n) =
                    make_float2(acc[mf][f][2], acc[mf][f][3]);
            }
        }
    }
}

// ---------------- kernel 3: reduce split-K + colsum + L2 normalize ----------------
__global__ void __launch_bounds__(320) normalize_kernel(float* __restrict__ out) {
    __shared__ float red[10];
    __shared__ float s_inv;
    const int r = blockIdx.x;
    const int tid = threadIdx.x;           // one column per thread (tid < 300 active)
    float v = 0.0f;
    if (tid < D_DIM) {
        v = 0.5f * g_colsum[tid];
#pragma unroll
        for (int zz = 0; zz < NSPLIT; zz++)
            v += g_part[((size_t)zz * B_DIM + r) * D_PITCH + tid];
    }
    float ss = v * v;
#pragma unroll
    for (int o = 16; o; o >>= 1) ss += __shfl_xor_sync(0xffffffffu, ss, o);
    if ((tid & 31) == 0) red[tid >> 5] = ss;
    __syncthreads();
    if (tid < 32) {
        float s = (tid < 10) ? red[tid] : 0.0f;
#pragma unroll
        for (int o = 16; o; o >>= 1) s += __shfl_xor_sync(0xffffffffu, s, o);
        if (tid == 0) s_inv = 1.0f / (sqrtf(s) + EPS);
    }
    __syncthreads();
    if (tid < D_DIM) out[(size_t)r * D_DIM + tid] = v * s_inv;
}

// ---------------- host launch ----------------
extern "C" void kernel_launch(void* const* d_in, const int* in_sizes, int n_in,
                              void* d_out, int out_size) {
    const float* labels = (const float*)d_in[0];
    const float* weight = (const float*)d_in[1];
    if (n_in >= 2 && in_sizes[0] == V_DIM * D_DIM) {  // defensive order swap
        const float* t = labels; labels = weight; weight = t;
    }

    cudaFuncSetAttribute(gemm_kernel, cudaFuncAttributeMaxDynamicSharedMemorySize,
                         SMEM_TOTAL);

    void* colsum_ptr = nullptr;
    cudaGetSymbolAddress(&colsum_ptr, g_colsum);
    cudaMemsetAsync(colsum_ptr, 0, D_PITCH * sizeof(float));

    prep_kernel<<<dim3(NKB, 5), 256>>>(weight);
    gemm_kernel<<<dim3(M_TILES, NSPLIT), 256, SMEM_TOTAL>>>(labels);
    normalize_kernel<<<B_DIM, 320>>>((float*)d_out);
}